// round 13
// baseline (speedup 1.0000x reference)
#include <cuda_runtime.h>
#include <cuda_bf16.h>

#define TSEQ   2048
#define BATCH  4096
#define HDIM   32
#define STAGE  16
#define NSTAGE (TSEQ / STAGE)
#define NBMAX  4
#define HROW   40        // 32 h + 3 x + 1.0 + pad (160B row, 16B aligned)
#define NB28BLOCKS 100   // blocks carrying 28 rows; remaining 48 carry 27

typedef unsigned long long ull;

// ---------- packed f32x2 helpers ----------
__device__ __forceinline__ ull pack2(float lo, float hi) {
    ull r;
    asm("mov.b64 %0, {%1, %2};" : "=l"(r) : "f"(lo), "f"(hi));
    return r;
}
__device__ __forceinline__ void unpack2(ull v, float& lo, float& hi) {
    asm("mov.b64 {%0, %1}, %2;" : "=f"(lo), "=f"(hi) : "l"(v));
}
__device__ __forceinline__ ull ffma2(ull a, ull b, ull c) {
    ull d;
    asm("fma.rn.f32x2 %0, %1, %2, %3;" : "=l"(d) : "l"(a), "l"(b), "l"(c));
    return d;
}
__device__ __forceinline__ ull mul2(ull a, ull b) {
    ull d;
    asm("mul.rn.f32x2 %0, %1, %2;" : "=l"(d) : "l"(a), "l"(b));
    return d;
}
// 4-byte async copy global -> shared (no destination register)
__device__ __forceinline__ void cp_async4(unsigned int saddr, const void* gaddr) {
    asm volatile("cp.async.ca.shared.global [%0], [%1], 4;"
                 :: "r"(saddr), "l"(gaddr));
}
__device__ __forceinline__ void cp_async_commit() {
    asm volatile("cp.async.commit_group;");
}
__device__ __forceinline__ void cp_async_wait0() {
    asm volatile("cp.async.wait_group 0;");
}

// ---------- single-MUFU tanh (sm_75+) ----------
__device__ __forceinline__ float tanhf_fast(float x) {
    float y;
    asm("tanh.approx.f32 %0, %1;" : "=f"(y) : "f"(x));
    return y;
}
// sigmoid(x) = 0.5*tanh(x/2) + 0.5 ; the /2 pre-folded into weights+bias.
__device__ __forceinline__ float sig_from_half(float xh) {
    return fmaf(0.5f, tanhf_fast(xh), 0.5f);
}

// One warp processes NB batch rows through all 2048 steps.
// EXTENDED-STATE matvec: preact = W·[h(32); x(3); 1] as 9 uniform groups of
// (1 ulonglong2 load + 8 FFMA2). No separate input affine. Weights k-packed
// per gate (18 f32x2 pairs; pair 16=(wx0,wx1), pair 17=(wx2,bias)).
// Sigmoid rows pre-scaled by 0.5. All W registers: 144 (same as before).
template <int NB>
__device__ __forceinline__ void lstm_run(
    const float* __restrict__ x,
    const float* __restrict__ W_ih,
    const float* __restrict__ W_hh,
    const float* __restrict__ b_ih,
    const float* __restrict__ b_hh,
    float* __restrict__ out,
    float (*hs)[NBMAX][HROW],        // [2][NBMAX][40] parity-buffered state
    float (*xs)[NBMAX][STAGE][4],    // [2][NBMAX][16][4] double-buffered x
    int row0, int lane)
{
    constexpr int NE = NB * STAGE * 3;       // x elements per stage
    constexpr int NI = (NE + 31) / 32;       // cp.async iterations per lane

    // PyTorch gate rows for this lane: i, f, g, o
    const int r0 = lane;             // i  (sigmoid -> 0.5)
    const int r1 = HDIM + lane;      // f  (sigmoid -> 0.5)
    const int r2 = 2 * HDIM + lane;  // g  (tanh    -> 1.0)
    const int r3 = 3 * HDIM + lane;  // o  (sigmoid -> 0.5)

    // ---- weights: 18 k-packed pairs per gate (recurrent + input + bias) ----
    ull wkI[18], wkF[18], wkG[18], wkO[18];
#pragma unroll
    for (int m = 0; m < 16; m++) {
        wkI[m] = pack2(0.5f * W_hh[r0 * HDIM + 2 * m], 0.5f * W_hh[r0 * HDIM + 2 * m + 1]);
        wkF[m] = pack2(0.5f * W_hh[r1 * HDIM + 2 * m], 0.5f * W_hh[r1 * HDIM + 2 * m + 1]);
        wkG[m] = pack2(       W_hh[r2 * HDIM + 2 * m],        W_hh[r2 * HDIM + 2 * m + 1]);
        wkO[m] = pack2(0.5f * W_hh[r3 * HDIM + 2 * m], 0.5f * W_hh[r3 * HDIM + 2 * m + 1]);
    }
    wkI[16] = pack2(0.5f * W_ih[r0 * 3 + 0], 0.5f * W_ih[r0 * 3 + 1]);
    wkF[16] = pack2(0.5f * W_ih[r1 * 3 + 0], 0.5f * W_ih[r1 * 3 + 1]);
    wkG[16] = pack2(       W_ih[r2 * 3 + 0],        W_ih[r2 * 3 + 1]);
    wkO[16] = pack2(0.5f * W_ih[r3 * 3 + 0], 0.5f * W_ih[r3 * 3 + 1]);
    wkI[17] = pack2(0.5f * W_ih[r0 * 3 + 2], 0.5f * (b_ih[r0] + b_hh[r0]));
    wkF[17] = pack2(0.5f * W_ih[r1 * 3 + 2], 0.5f * (b_ih[r1] + b_hh[r1]));
    wkG[17] = pack2(       W_ih[r2 * 3 + 2],        (b_ih[r2] + b_hh[r2]));
    wkO[17] = pack2(0.5f * W_ih[r3 * 3 + 2], 0.5f * (b_ih[r3] + b_hh[r3]));

    unsigned int xs_s[2];
    xs_s[0] = (unsigned int)__cvta_generic_to_shared(&xs[0][0][0][0]);
    xs_s[1] = (unsigned int)__cvta_generic_to_shared(&xs[1][0][0][0]);

    float c[NB];
#pragma unroll
    for (int b = 0; b < NB; b++) {
        c[b] = 0.0f;
        hs[0][b][lane] = 0.0f;
        if (lane == 0) {                 // constant-1 slot, both parity buffers
            hs[0][b][35] = 1.0f;
            hs[1][b][35] = 1.0f;
        }
    }

    // ---- stage 0 of x via cp.async ----
#pragma unroll
    for (int it = 0; it < NI; it++) {
        int idx = it * 32 + lane;
        if (idx < NE) {
            int b   = idx / (STAGE * 3);
            int rem = idx % (STAGE * 3);
            int t   = rem / 3, i = rem % 3;
            cp_async4(xs_s[0] + (unsigned)((b * STAGE + t) * 4 + i) * 4u,
                      x + (size_t)(row0 + b) * TSEQ * 3 + rem);
        }
    }
    cp_async_commit();
    cp_async_wait0();
    __syncwarp();
    // seed x_0 into the step-0 state buffer
#pragma unroll
    for (int b = 0; b < NB; b++)
        if (lane < 3) hs[0][b][32 + lane] = xs[0][b][0][lane];
    __syncwarp();

    int buf = 0;
#pragma unroll 1
    for (int s = 0; s < NSTAGE; s++) {
        // ---- prefetch next stage into the other buffer (fire and forget) ----
        if (s + 1 < NSTAGE) {
#pragma unroll
            for (int it = 0; it < NI; it++) {
                int idx = it * 32 + lane;
                if (idx < NE) {
                    int b   = idx / (STAGE * 3);
                    int rem = idx % (STAGE * 3);
                    int t   = rem / 3, i = rem % 3;
                    cp_async4(xs_s[buf ^ 1] + (unsigned)((b * STAGE + t) * 4 + i) * 4u,
                              x + (size_t)(row0 + b) * TSEQ * 3
                                + (size_t)(s + 1) * STAGE * 3 + rem);
                }
            }
            cp_async_commit();
        }

#pragma unroll 1
        for (int tt = 0; tt < STAGE; tt++) {
            const int rb = tt & 1;
            const int wb = rb ^ 1;

            ull accI[NB], accF[NB], accG[NB], accO[NB];

            // ---- group 0 seeds the accumulators (mul + fma, no zero-init) ----
#pragma unroll
            for (int b = 0; b < NB; b++) {
                ulonglong2 hd = *reinterpret_cast<const ulonglong2*>(&hs[rb][b][0]);
                accI[b] = mul2(wkI[0], hd.x);
                accF[b] = mul2(wkF[0], hd.x);
                accG[b] = mul2(wkG[0], hd.x);
                accO[b] = mul2(wkO[0], hd.x);
                accI[b] = ffma2(wkI[1], hd.y, accI[b]);
                accF[b] = ffma2(wkF[1], hd.y, accF[b]);
                accG[b] = ffma2(wkG[1], hd.y, accG[b]);
                accO[b] = ffma2(wkO[1], hd.y, accO[b]);
            }
            // ---- groups 1..8: remaining h, then x and bias (uniform code) ----
#pragma unroll
            for (int g = 1; g < 9; g++) {
#pragma unroll
                for (int b = 0; b < NB; b++) {
                    ulonglong2 hd = *reinterpret_cast<const ulonglong2*>(&hs[rb][b][4 * g]);
                    accI[b] = ffma2(wkI[2 * g],     hd.x, accI[b]);
                    accF[b] = ffma2(wkF[2 * g],     hd.x, accF[b]);
                    accG[b] = ffma2(wkG[2 * g],     hd.x, accG[b]);
                    accO[b] = ffma2(wkO[2 * g],     hd.x, accO[b]);
                    accI[b] = ffma2(wkI[2 * g + 1], hd.y, accI[b]);
                    accF[b] = ffma2(wkF[2 * g + 1], hd.y, accF[b]);
                    accG[b] = ffma2(wkG[2 * g + 1], hd.y, accG[b]);
                    accO[b] = ffma2(wkO[2 * g + 1], hd.y, accO[b]);
                }
            }

            // ---- horizontal merge + activations + state update + x forward ----
#pragma unroll
            for (int b = 0; b < NB; b++) {
                float ilo, ihi, flo, fhi, glo, ghi, olo, ohi;
                unpack2(accI[b], ilo, ihi);
                unpack2(accF[b], flo, fhi);
                unpack2(accG[b], glo, ghi);
                unpack2(accO[b], olo, ohi);
                float ig = sig_from_half(ilo + ihi);
                float fg = sig_from_half(flo + fhi);
                float gg = tanhf_fast(glo + ghi);
                float og = sig_from_half(olo + ohi);
                c[b] = fmaf(fg, c[b], ig * gg);
                hs[wb][b][lane] = og * tanhf_fast(c[b]);
                if (tt + 1 < STAGE && lane < 3)
                    hs[wb][b][32 + lane] = xs[buf][b][tt + 1][lane];
            }
            __syncwarp();   // state published before next step's reads
        }

        // ---- stage boundary: flip x buffer, seed x_0 of next stage ----
        if (s + 1 < NSTAGE) {
            cp_async_wait0();
            __syncwarp();
            buf ^= 1;
#pragma unroll
            for (int b = 0; b < NB; b++)
                if (lane < 3) hs[0][b][32 + lane] = xs[buf][b][0][lane];
            __syncwarp();
        }
    }

    // Last step (tt=15) wrote parity buffer 0.
#pragma unroll
    for (int b = 0; b < NB; b++)
        out[(size_t)(row0 + b) * HDIM + lane] = hs[0][b][lane];
}

// Row distribution within a block. wid%4 -> SMSP, so wid i pairs with wid i+4.
// 28-row blocks: NB = 4,4,4,4,3,3,3,3  -> every SMSP pair carries 4+3 = 7 rows.
// 27-row blocks: NB = 4,4,4,3,3,3,3,3  -> pairs 7,7,7,6.
__device__ __constant__ int NB28[8]  = {4, 4, 4, 4, 3, 3, 3, 3};
__device__ __constant__ int OFF28[8] = {0, 4, 8, 12, 16, 19, 22, 25};
__device__ __constant__ int NB27[8]  = {4, 4, 4, 3, 3, 3, 3, 3};
__device__ __constant__ int OFF27[8] = {0, 4, 8, 12, 15, 18, 21, 24};

// 148 blocks x 256 threads: one block per SM, 2 warps per SMSP with
// controlled pairing; single wave, zero tail.
__global__ void __launch_bounds__(256, 1)
lstm_kernel(const float* __restrict__ x,
            const float* __restrict__ W_ih,
            const float* __restrict__ W_hh,
            const float* __restrict__ b_ih,
            const float* __restrict__ b_hh,
            float* __restrict__ out)
{
    __shared__ __align__(16) float hsm[8][2][NBMAX][HROW];
    __shared__ __align__(16) float xsm[8][2][NBMAX][STAGE][4];

    const int wid  = threadIdx.x >> 5;
    const int lane = threadIdx.x & 31;
    const int bid  = blockIdx.x;

    int row0, nb;
    if (bid < NB28BLOCKS) {
        row0 = bid * 28 + OFF28[wid];
        nb   = NB28[wid];
    } else {
        row0 = NB28BLOCKS * 28 + (bid - NB28BLOCKS) * 27 + OFF27[wid];
        nb   = NB27[wid];
    }

    if (nb == 4) {
        lstm_run<4>(x, W_ih, W_hh, b_ih, b_hh, out, hsm[wid], xsm[wid], row0, lane);
    } else {
        lstm_run<3>(x, W_ih, W_hh, b_ih, b_hh, out, hsm[wid], xsm[wid], row0, lane);
    }
}

extern "C" void kernel_launch(void* const* d_in, const int* in_sizes, int n_in,
                              void* d_out, int out_size)
{
    const float* x    = (const float*)d_in[0];
    const float* W_ih = (const float*)d_in[1];
    const float* W_hh = (const float*)d_in[2];
    const float* b_ih = (const float*)d_in[3];
    const float* b_hh = (const float*)d_in[4];
    float* out = (float*)d_out;

    lstm_kernel<<<148, 256>>>(x, W_ih, W_hh, b_ih, b_hh, out);
}

// round 14
// speedup vs baseline: 1.0798x; 1.0798x over previous
#include <cuda_runtime.h>
#include <cuda_bf16.h>

#define TSEQ   2048
#define BATCH  4096
#define HDIM   32
#define STAGE  32
#define NSTAGE (TSEQ / STAGE)
#define NBMAX  4
#define NB28BLOCKS 100   // blocks carrying 28 rows; remaining 48 carry 27

typedef unsigned long long ull;

// ---------- packed f32x2 helpers ----------
__device__ __forceinline__ ull pack2(float lo, float hi) {
    ull r;
    asm("mov.b64 %0, {%1, %2};" : "=l"(r) : "f"(lo), "f"(hi));
    return r;
}
__device__ __forceinline__ void unpack2(ull v, float& lo, float& hi) {
    asm("mov.b64 {%0, %1}, %2;" : "=f"(lo), "=f"(hi) : "l"(v));
}
__device__ __forceinline__ ull ffma2(ull a, ull b, ull c) {
    ull d;
    asm("fma.rn.f32x2 %0, %1, %2, %3;" : "=l"(d) : "l"(a), "l"(b), "l"(c));
    return d;
}
// 4-byte async copy global -> shared (no destination register)
__device__ __forceinline__ void cp_async4(unsigned int saddr, const void* gaddr) {
    asm volatile("cp.async.ca.shared.global [%0], [%1], 4;"
                 :: "r"(saddr), "l"(gaddr));
}
__device__ __forceinline__ void cp_async_commit() {
    asm volatile("cp.async.commit_group;");
}
__device__ __forceinline__ void cp_async_wait0() {
    asm volatile("cp.async.wait_group 0;");
}
// compiler-only ordering fence: warp is fully converged in the step loop, so
// same-warp STS -> LDS ordering is guaranteed by program order; we only need
// to stop the compiler from reordering across the step edge.
__device__ __forceinline__ void step_fence() {
    asm volatile("" ::: "memory");
}

// ---------- single-MUFU tanh (sm_75+) ----------
__device__ __forceinline__ float tanhf_fast(float x) {
    float y;
    asm("tanh.approx.f32 %0, %1;" : "=f"(y) : "f"(x));
    return y;
}
// sigmoid(x) = 0.5*tanh(x/2) + 0.5 ; the /2 pre-folded into weights+bias.
__device__ __forceinline__ float sig_from_half(float xh) {
    return fmaf(0.5f, tanhf_fast(xh), 0.5f);
}

// One warp processes NB batch rows through all 2048 steps.
// DUPLICATION-FREE k-packed layout: h stored as plain f32; one ulonglong2
// load gives two ready f32x2 operands (adjacent k pairs). Weights packed over
// adjacent k per gate. 4 accumulators per row (16 chains). Horizontal FADD
// merges even/odd partial sums. Sigmoid rows pre-scaled by 0.5.
// W_hh fully register-resident (128 regs/lane).
template <int NB>
__device__ __forceinline__ void lstm_run(
    const float* __restrict__ x,
    const float* __restrict__ W_ih,
    const float* __restrict__ W_hh,
    const float* __restrict__ b_ih,
    const float* __restrict__ b_hh,
    float* __restrict__ out,
    float (*hs)[NBMAX][HDIM],        // [2][NBMAX][32] plain f32, parity-buffered
    float (*xs)[NBMAX][STAGE][4],    // [2][NBMAX][32][4] double-buffered
    int row0, int lane)
{
    constexpr int NE = NB * STAGE * 3;       // x elements per stage (mult of 32)
    constexpr int NI = NE / 32;              // cp.async iterations per lane

    // PyTorch gate rows for this lane: i, f, g, o
    const int r0 = lane;             // i  (sigmoid -> 0.5)
    const int r1 = HDIM + lane;      // f  (sigmoid -> 0.5)
    const int r2 = 2 * HDIM + lane;  // g  (tanh    -> 1.0)
    const int r3 = 3 * HDIM + lane;  // o  (sigmoid -> 0.5)

    // ---- recurrent weights, packed over adjacent k per gate ----
    ull wkI[16], wkF[16], wkG[16], wkO[16];
#pragma unroll
    for (int m = 0; m < 16; m++) {
        wkI[m] = pack2(0.5f * W_hh[r0 * HDIM + 2 * m], 0.5f * W_hh[r0 * HDIM + 2 * m + 1]);
        wkF[m] = pack2(0.5f * W_hh[r1 * HDIM + 2 * m], 0.5f * W_hh[r1 * HDIM + 2 * m + 1]);
        wkG[m] = pack2(       W_hh[r2 * HDIM + 2 * m],        W_hh[r2 * HDIM + 2 * m + 1]);
        wkO[m] = pack2(0.5f * W_hh[r3 * HDIM + 2 * m], 0.5f * W_hh[r3 * HDIM + 2 * m + 1]);
    }
    // ---- input weights + combined bias (scalars) ----
    float wxi[3], wxf[3], wxg[3], wxo[3];
#pragma unroll
    for (int i = 0; i < 3; i++) {
        wxi[i] = 0.5f * W_ih[r0 * 3 + i];
        wxf[i] = 0.5f * W_ih[r1 * 3 + i];
        wxg[i] =        W_ih[r2 * 3 + i];
        wxo[i] = 0.5f * W_ih[r3 * 3 + i];
    }
    const float bI = 0.5f * (b_ih[r0] + b_hh[r0]);
    const float bF = 0.5f * (b_ih[r1] + b_hh[r1]);
    const float bG =        (b_ih[r2] + b_hh[r2]);
    const float bO = 0.5f * (b_ih[r3] + b_hh[r3]);

    unsigned int xs_s[2];
    xs_s[0] = (unsigned int)__cvta_generic_to_shared(&xs[0][0][0][0]);
    xs_s[1] = (unsigned int)__cvta_generic_to_shared(&xs[1][0][0][0]);

    float c[NB];
#pragma unroll
    for (int b = 0; b < NB; b++) {
        c[b] = 0.0f;
        hs[0][b][lane] = 0.0f;
    }

    // ---- stage 0 of x via cp.async (loops are exact: no divergence) ----
#pragma unroll
    for (int it = 0; it < NI; it++) {
        int idx = it * 32 + lane;
        int b   = idx / (STAGE * 3);
        int rem = idx % (STAGE * 3);
        int t   = rem / 3, i = rem % 3;
        cp_async4(xs_s[0] + (unsigned)((b * STAGE + t) * 4 + i) * 4u,
                  x + (size_t)(row0 + b) * TSEQ * 3 + rem);
    }
    cp_async_commit();
    cp_async_wait0();
    __syncwarp();

    int buf = 0;
#pragma unroll 1
    for (int s = 0; s < NSTAGE; s++) {
        // ---- prefetch next stage into the other buffer (fire and forget) ----
        if (s + 1 < NSTAGE) {
#pragma unroll
            for (int it = 0; it < NI; it++) {
                int idx = it * 32 + lane;
                int b   = idx / (STAGE * 3);
                int rem = idx % (STAGE * 3);
                int t   = rem / 3, i = rem % 3;
                cp_async4(xs_s[buf ^ 1] + (unsigned)((b * STAGE + t) * 4 + i) * 4u,
                          x + (size_t)(row0 + b) * TSEQ * 3
                            + (size_t)(s + 1) * STAGE * 3 + rem);
            }
            cp_async_commit();
        }

#pragma unroll 1
        for (int tt = 0; tt < STAGE; tt++) {
            const int rb = tt & 1;
            const int wb = rb ^ 1;

            // ---- affine seeds accumulators as (aff, 0) ----
            ull accI[NB], accF[NB], accG[NB], accO[NB];
#pragma unroll
            for (int b = 0; b < NB; b++) {
                float4 xv = *reinterpret_cast<const float4*>(&xs[buf][b][tt][0]);
                accI[b] = pack2(fmaf(xv.x, wxi[0], fmaf(xv.y, wxi[1], fmaf(xv.z, wxi[2], bI))), 0.0f);
                accF[b] = pack2(fmaf(xv.x, wxf[0], fmaf(xv.y, wxf[1], fmaf(xv.z, wxf[2], bF))), 0.0f);
                accG[b] = pack2(fmaf(xv.x, wxg[0], fmaf(xv.y, wxg[1], fmaf(xv.z, wxg[2], bG))), 0.0f);
                accO[b] = pack2(fmaf(xv.x, wxo[0], fmaf(xv.y, wxo[1], fmaf(xv.z, wxo[2], bO))), 0.0f);
            }

            // ---- recurrent matvec: kk-outer (8 groups of 4 k), rows inner.
            // One ulonglong2 load = 2 f32x2 operands of DISTINCT adjacent h. ----
#pragma unroll
            for (int g = 0; g < 8; g++) {
#pragma unroll
                for (int b = 0; b < NB; b++) {
                    ulonglong2 hd = *reinterpret_cast<const ulonglong2*>(&hs[rb][b][4 * g]);
                    accI[b] = ffma2(wkI[2 * g],     hd.x, accI[b]);
                    accF[b] = ffma2(wkF[2 * g],     hd.x, accF[b]);
                    accG[b] = ffma2(wkG[2 * g],     hd.x, accG[b]);
                    accO[b] = ffma2(wkO[2 * g],     hd.x, accO[b]);
                    accI[b] = ffma2(wkI[2 * g + 1], hd.y, accI[b]);
                    accF[b] = ffma2(wkF[2 * g + 1], hd.y, accF[b]);
                    accG[b] = ffma2(wkG[2 * g + 1], hd.y, accG[b]);
                    accO[b] = ffma2(wkO[2 * g + 1], hd.y, accO[b]);
                }
            }

            // ---- horizontal merge + activations + state update ----
#pragma unroll
            for (int b = 0; b < NB; b++) {
                float ilo, ihi, flo, fhi, glo, ghi, olo, ohi;
                unpack2(accI[b], ilo, ihi);
                unpack2(accF[b], flo, fhi);
                unpack2(accG[b], glo, ghi);
                unpack2(accO[b], olo, ohi);
                float ig = sig_from_half(ilo + ihi);
                float fg = sig_from_half(flo + fhi);
                float gg = tanhf_fast(glo + ghi);
                float og = sig_from_half(olo + ohi);
                c[b] = fmaf(fg, c[b], ig * gg);
                hs[wb][b][lane] = og * tanhf_fast(c[b]);
            }
            // converged warp: program order suffices for STS->LDS; fence the
            // compiler only (saves a WARPSYNC per step on the critical path)
            step_fence();
        }

        // ---- flip x buffer once the prefetch has landed ----
        if (s + 1 < NSTAGE) {
            cp_async_wait0();
            __syncwarp();
            buf ^= 1;
        }
    }

    // STAGE even: last step wrote parity buffer 0.
#pragma unroll
    for (int b = 0; b < NB; b++)
        out[(size_t)(row0 + b) * HDIM + lane] = hs[0][b][lane];
}

// Row distribution within a block. wid%4 -> SMSP, so wid i pairs with wid i+4.
// 28-row blocks: NB = 4,4,4,4,3,3,3,3  -> every SMSP pair carries 4+3 = 7 rows.
// 27-row blocks: NB = 4,4,4,3,3,3,3,3  -> pairs 7,7,7,6.
__device__ __constant__ int NB28[8]  = {4, 4, 4, 4, 3, 3, 3, 3};
__device__ __constant__ int OFF28[8] = {0, 4, 8, 12, 16, 19, 22, 25};
__device__ __constant__ int NB27[8]  = {4, 4, 4, 3, 3, 3, 3, 3};
__device__ __constant__ int OFF27[8] = {0, 4, 8, 12, 15, 18, 21, 24};

// 148 blocks x 256 threads: one block per SM, 2 warps per SMSP with
// controlled pairing; single wave, zero tail.
__global__ void __launch_bounds__(256, 1)
lstm_kernel(const float* __restrict__ x,
            const float* __restrict__ W_ih,
            const float* __restrict__ W_hh,
            const float* __restrict__ b_ih,
            const float* __restrict__ b_hh,
            float* __restrict__ out)
{
    __shared__ __align__(16) float hsm[8][2][NBMAX][HDIM];
    __shared__ __align__(16) float xsm[8][2][NBMAX][STAGE][4];

    const int wid  = threadIdx.x >> 5;
    const int lane = threadIdx.x & 31;
    const int bid  = blockIdx.x;

    int row0, nb;
    if (bid < NB28BLOCKS) {
        row0 = bid * 28 + OFF28[wid];
        nb   = NB28[wid];
    } else {
        row0 = NB28BLOCKS * 28 + (bid - NB28BLOCKS) * 27 + OFF27[wid];
        nb   = NB27[wid];
    }

    if (nb == 4) {
        lstm_run<4>(x, W_ih, W_hh, b_ih, b_hh, out, hsm[wid], xsm[wid], row0, lane);
    } else {
        lstm_run<3>(x, W_ih, W_hh, b_ih, b_hh, out, hsm[wid], xsm[wid], row0, lane);
    }
}

extern "C" void kernel_launch(void* const* d_in, const int* in_sizes, int n_in,
                              void* d_out, int out_size)
{
    const float* x    = (const float*)d_in[0];
    const float* W_ih = (const float*)d_in[1];
    const float* W_hh = (const float*)d_in[2];
    const float* b_ih = (const float*)d_in[3];
    const float* b_hh = (const float*)d_in[4];
    float* out = (float*)d_out;

    lstm_kernel<<<148, 256>>>(x, W_ih, W_hh, b_ih, b_hh, out);
}

// round 15
// speedup vs baseline: 1.5858x; 1.4686x over previous
#include <cuda_runtime.h>
#include <cuda_bf16.h>

#define TSEQ   2048
#define BATCH  4096
#define HDIM   32
#define STAGE  32
#define NSTAGE (TSEQ / STAGE)
#define ROWS   8          // n8 MMA columns = batch rows per warp
#define NWARPS 4
#define XPAD   33         // x row pad (bank spread)
#define HPAD   40         // h row pad in halves (80B stride, bank spread)

typedef unsigned int   u32;
typedef unsigned short u16;

// ---------- activations ----------
__device__ __forceinline__ float tanhf_fast(float x) {
    float y; asm("tanh.approx.f32 %0, %1;" : "=f"(y) : "f"(x)); return y;
}
// sigmoid(x) = 0.5*tanh(x/2) + 0.5 ; the /2 pre-folded into weights+bias.
__device__ __forceinline__ float sig_from_half(float xh) {
    return fmaf(0.5f, tanhf_fast(xh), 0.5f);
}

// ---------- bf16 split helpers ----------
// packed bf16x2: element0 (lower k) in low 16 bits
__device__ __forceinline__ u32 pack_hi_trunc(float e0, float e1) {
    return (__float_as_uint(e0) >> 16) | (__float_as_uint(e1) & 0xFFFF0000u);
}
__device__ __forceinline__ float trunc_bf(float a) {
    return __uint_as_float(__float_as_uint(a) & 0xFFFF0000u);
}
__device__ __forceinline__ u32 pack_bf16_rn(float e0, float e1) {
    u32 r; asm("cvt.rn.bf16x2.f32 %0, %1, %2;" : "=r"(r) : "f"(e1), "f"(e0)); return r;
}
__device__ __forceinline__ u16 bf16_bits(float a) {
    __nv_bfloat16 v = __float2bfloat16(a);
    return *reinterpret_cast<u16*>(&v);
}

// ---------- async copy ----------
__device__ __forceinline__ void cp_async4(u32 saddr, const void* gaddr) {
    asm volatile("cp.async.ca.shared.global [%0], [%1], 4;" :: "r"(saddr), "l"(gaddr));
}
__device__ __forceinline__ void cp_async_commit() { asm volatile("cp.async.commit_group;"); }
__device__ __forceinline__ void cp_async_wait0()  { asm volatile("cp.async.wait_group 0;"); }
// converged warp: program order covers STS->LDS; fence the compiler only
__device__ __forceinline__ void step_fence() { asm volatile("" ::: "memory"); }

// m16n8k16 bf16 MMA, fp32 accumulate (D += A @ B)
#define MMA16816(d, a, b0, b1)                                               \
    asm volatile("mma.sync.aligned.m16n8k16.row.col.f32.bf16.bf16.f32 "     \
        "{%0,%1,%2,%3}, {%4,%5,%6,%7}, {%8,%9}, {%0,%1,%2,%3};"             \
        : "+f"((d)[0]), "+f"((d)[1]), "+f"((d)[2]), "+f"((d)[3])            \
        : "r"((a)[0]), "r"((a)[1]), "r"((a)[2]), "r"((a)[3]), "r"(b0), "r"(b1))

// One warp = 8 batch rows through all 2048 steps, entirely warp-local.
// A = W_hh (128x32) static in A-fragment registers, split bf16 hi+lo.
// B = h^T (32x8) rebuilt per step from smem bf16 hi/lo arrays.
// D-fragment: lane l holds all 4 gates for units {g,g+8,g+16,g+24},
// rows {2t,2t+1} -> activations and state updates are lane-local.
__global__ void __launch_bounds__(128, 1)
lstm_mma_kernel(const float* __restrict__ x,
                const float* __restrict__ W_ih,
                const float* __restrict__ W_hh,
                const float* __restrict__ b_ih,
                const float* __restrict__ b_hh,
                float* __restrict__ out)
{
    __shared__ __align__(16) float  xs[NWARPS][2][ROWS][XPAD][4];
    __shared__ __align__(4)  u16    hhi[NWARPS][ROWS][HPAD];
    __shared__ __align__(4)  u16    hlo[NWARPS][ROWS][HPAD];
    __shared__ __align__(16) float4 wxb[4 * HDIM];   // {wx0,wx1,wx2,bias} per gate row

    const int tid  = threadIdx.x;
    const int wid  = tid >> 5;
    const int lane = tid & 31;
    const int g    = lane >> 2;   // groupID
    const int t    = lane & 3;    // threadID_in_group

    // input-weight + bias table (sigmoid rows pre-scaled by 0.5)
    {
        int m = tid;              // 128 threads, 128 gate rows
        float s = ((m >> 5) == 2) ? 1.0f : 0.5f;
        wxb[m] = make_float4(s * W_ih[m * 3 + 0], s * W_ih[m * 3 + 1],
                             s * W_ih[m * 3 + 2], s * (b_ih[m] + b_hh[m]));
    }
    // zero h arrays (h0 = 0)
    for (int i2 = lane; i2 < ROWS * HPAD; i2 += 32) {
        hhi[wid][i2 / HPAD][i2 % HPAD] = 0;
        hlo[wid][i2 / HPAD][i2 % HPAD] = 0;
    }
    __syncthreads();

    // ---- build static A-fragments: W_hh split hi/lo, sigmoid rows *0.5 ----
    u32 Ahi[8][2][4], Alo[8][2][4];
#pragma unroll
    for (int T = 0; T < 8; T++) {
#pragma unroll
        for (int Kt = 0; Kt < 2; Kt++) {
            int k0 = 16 * Kt + 2 * t;
#pragma unroll
            for (int r = 0; r < 4; r++) {
                int m = 16 * T + g + ((r & 1) ? 8 : 0);
                int k = k0 + ((r >> 1) ? 8 : 0);
                float s  = ((m >> 5) == 2) ? 1.0f : 0.5f;
                float w0 = s * W_hh[m * HDIM + k];
                float w1 = s * W_hh[m * HDIM + k + 1];
                Ahi[T][Kt][r] = pack_hi_trunc(w0, w1);
                Alo[T][Kt][r] = pack_bf16_rn(w0 - trunc_bf(w0), w1 - trunc_bf(w1));
            }
        }
    }

    const int row0 = (blockIdx.x * NWARPS + wid) * ROWS;
    u32 xbase[2];
    xbase[0] = (u32)__cvta_generic_to_shared(&xs[wid][0][0][0][0]);
    xbase[1] = (u32)__cvta_generic_to_shared(&xs[wid][1][0][0][0]);

    // ---- stage 0 of x (ROWS*STAGE*3 = 768 elems, 24 per lane, exact) ----
#pragma unroll
    for (int it = 0; it < 24; it++) {
        int idx = it * 32 + lane;
        int b   = idx / (STAGE * 3);
        int rem = idx % (STAGE * 3);
        int ts  = rem / 3, i = rem % 3;
        cp_async4(xbase[0] + (u32)(((b * XPAD + ts) * 4 + i) * 4),
                  x + (size_t)(row0 + b) * TSEQ * 3 + rem);
    }
    cp_async_commit();
    cp_async_wait0();
    __syncwarp();

    float cst[8], hout[8];
#pragma unroll
    for (int i = 0; i < 8; i++) { cst[i] = 0.0f; hout[i] = 0.0f; }

    int buf = 0;
#pragma unroll 1
    for (int s = 0; s < NSTAGE; s++) {
        // prefetch next stage (fire and forget)
        if (s + 1 < NSTAGE) {
#pragma unroll
            for (int it = 0; it < 24; it++) {
                int idx = it * 32 + lane;
                int b   = idx / (STAGE * 3);
                int rem = idx % (STAGE * 3);
                int ts  = rem / 3, i = rem % 3;
                cp_async4(xbase[buf ^ 1] + (u32)(((b * XPAD + ts) * 4 + i) * 4),
                          x + (size_t)(row0 + b) * TSEQ * 3
                            + (size_t)(s + 1) * STAGE * 3 + rem);
            }
            cp_async_commit();
        }

#pragma unroll 1
        for (int tt = 0; tt < STAGE; tt++) {
            // ---- B fragments: lane l reads (k, k+1) packed for row n=g ----
            u32 bh[2][2], bl[2][2];
#pragma unroll
            for (int Kt = 0; Kt < 2; Kt++) {
                int k = 16 * Kt + 2 * t;
                bh[Kt][0] = *(const u32*)&hhi[wid][g][k];
                bh[Kt][1] = *(const u32*)&hhi[wid][g][k + 8];
                bl[Kt][0] = *(const u32*)&hlo[wid][g][k];
                bl[Kt][1] = *(const u32*)&hlo[wid][g][k + 8];
            }

            // ---- affine + bias seeds D in fp32 (cols = rows 2t, 2t+1) ----
            float4 xa = *(const float4*)&xs[wid][buf][2 * t][tt][0];
            float4 xb = *(const float4*)&xs[wid][buf][2 * t + 1][tt][0];
            float d[8][4];
#pragma unroll
            for (int T = 0; T < 8; T++) {
#pragma unroll
                for (int h2 = 0; h2 < 2; h2++) {
                    float4 wv = wxb[16 * T + 8 * h2 + g];
                    d[T][2 * h2 + 0] = fmaf(wv.x, xa.x, fmaf(wv.y, xa.y, fmaf(wv.z, xa.z, wv.w)));
                    d[T][2 * h2 + 1] = fmaf(wv.x, xb.x, fmaf(wv.y, xb.y, fmaf(wv.z, xb.z, wv.w)));
                }
            }

            // ---- 48 HMMA: hi*hi + lo*hi + hi*lo (fp32 accumulate) ----
#pragma unroll
            for (int T = 0; T < 8; T++) {
#pragma unroll
                for (int Kt = 0; Kt < 2; Kt++) {
                    MMA16816(d[T], Ahi[T][Kt], bh[Kt][0], bh[Kt][1]);
                    MMA16816(d[T], Alo[T][Kt], bh[Kt][0], bh[Kt][1]);
                    MMA16816(d[T], Ahi[T][Kt], bl[Kt][0], bl[Kt][1]);
                }
            }

            // ---- activations + state update + h split/publish (lane-local) ----
#pragma unroll
            for (int Tp = 0; Tp < 2; Tp++) {
#pragma unroll
                for (int h2 = 0; h2 < 2; h2++) {
                    int u = 16 * Tp + 8 * h2 + g;
#pragma unroll
                    for (int dl = 0; dl < 2; dl++) {
                        int ci = (Tp * 2 + h2) * 2 + dl;
                        float iP = d[0 + Tp][2 * h2 + dl];
                        float fP = d[2 + Tp][2 * h2 + dl];
                        float gP = d[4 + Tp][2 * h2 + dl];
                        float oP = d[6 + Tp][2 * h2 + dl];
                        float ig = sig_from_half(iP);
                        float fg = sig_from_half(fP);
                        float gg = tanhf_fast(gP);
                        float og = sig_from_half(oP);
                        cst[ci] = fmaf(fg, cst[ci], ig * gg);
                        float hv = og * tanhf_fast(cst[ci]);
                        hout[ci] = hv;
                        int r = 2 * t + dl;
                        u32 hb = __float_as_uint(hv);
                        hhi[wid][r][u] = (u16)(hb >> 16);
                        hlo[wid][r][u] = bf16_bits(hv - __uint_as_float(hb & 0xFFFF0000u));
                    }
                }
            }
            step_fence();
        }

        if (s + 1 < NSTAGE) {
            cp_async_wait0();
            __syncwarp();
            buf ^= 1;
        }
    }

    // ---- final h (kept in registers in fp32) ----
#pragma unroll
    for (int Tp = 0; Tp < 2; Tp++)
#pragma unroll
        for (int h2 = 0; h2 < 2; h2++)
#pragma unroll
            for (int dl = 0; dl < 2; dl++) {
                int u = 16 * Tp + 8 * h2 + g;
                int r = 2 * t + dl;
                out[(size_t)(row0 + r) * HDIM + u] = hout[(Tp * 2 + h2) * 2 + dl];
            }
}

extern "C" void kernel_launch(void* const* d_in, const int* in_sizes, int n_in,
                              void* d_out, int out_size)
{
    const float* x    = (const float*)d_in[0];
    const float* W_ih = (const float*)d_in[1];
    const float* W_hh = (const float*)d_in[2];
    const float* b_ih = (const float*)d_in[3];
    const float* b_hh = (const float*)d_in[4];
    float* out = (float*)d_out;

    // 128 blocks x 128 threads: 512 warps x 8 rows = 4096; 1 warp per SMSP
    lstm_mma_kernel<<<BATCH / (NWARPS * ROWS), NWARPS * 32>>>(
        x, W_ih, W_hh, b_ih, b_hh, out);
}